// round 15
// baseline (speedup 1.0000x reference)
#include <cuda_runtime.h>

// Problem constants (fixed shapes for this problem instance)
#define BB 4
#define NV 8192
#define NF 8192
#define NP 2048
#define MIN_DIST 0.1f

#define CHUNK 128           // faces per shared-memory tile
#define NCHUNK (NF / CHUNK) // 64
#define THREADS 128
#define NPTS 4              // points per thread
#define PTS_PER_BLOCK (THREADS * NPTS)        // 512
#define PBLOCKS (NP / PTS_PER_BLOCK)          // 4
#define TOTAL_BLOCKS (PBLOCKS * NCHUNK * BB)  // 1024

// Scratch (no allocations allowed in kernel_launch)
__device__ float4       g_face[BB * NF];    // (n'x, n'y, n'z, off') per face
__device__ unsigned int g_minbits[BB * NP]; // unsigned-min of s-bits over faces
__device__ int          g_plist[BB * NP];   // compacted exterior point indices
__device__ int          g_pcount[BB];       // exterior count per batch
__device__ unsigned int g_ctr;              // last-block counter

__device__ __forceinline__ unsigned int umin2(unsigned int a, unsigned int b) {
    return a < b ? a : b; // IMNMX.U32
}

// ---------------------------------------------------------------------------
// Kernel 1: plane precompute (4 threads/face) + minbits init + exterior-point
// compaction. Compaction order is nondeterministic (atomicAdd) but the min
// reduction is order-independent, so the final output is deterministic.
// g_pcount is zeroed by the previous replay's finalize (and statically at t0).
// ---------------------------------------------------------------------------
__global__ __launch_bounds__(256)
void prep_kernel(const float* __restrict__ mesh_V,
                 const float* __restrict__ mesh_FN,
                 const int*   __restrict__ mesh_F,
                 const int*   __restrict__ ext) {
    int t = blockIdx.x * blockDim.x + threadIdx.x; // 0 .. BB*NF*4-1
    if (t < BB * NP) {
        g_minbits[t] = 0xFFFFFFFFu;
        int b = t / NP;
        if (ext[t] != 0) {
            int pos = atomicAdd(&g_pcount[b], 1);
            g_plist[b * NP + pos] = t - b * NP; // point index within batch
        }
    }

    int f = t >> 2;        // face id (0 .. BB*NF-1)
    int c = t & 3;         // coordinate lane (3 = offset slot)
    if (f >= BB * NF) return;

    int b = f / NF;
    const int* Fp = mesh_F + 3 * f;
    int i0 = Fp[0], i1 = Fp[1], i2 = Fp[2];
    const float* Vb = mesh_V + (size_t)b * NV * 3;

    float cc = 0.0f, nc = 0.0f;
    if (c < 3) {
        cc = (Vb[3 * i0 + c] + Vb[3 * i1 + c] + Vb[3 * i2 + c]) * (1.0f / 3.0f);
        nc = mesh_FN[3 * f + c];
    }

    // 4-lane group sums (groups are lane-aligned: lanes 4k..4k+3)
    float p  = cc * nc;
    float nn = nc * nc;
    p  += __shfl_xor_sync(0xFFFFFFFFu, p, 1);
    p  += __shfl_xor_sync(0xFFFFFFFFu, p, 2);
    nn += __shfl_xor_sync(0xFFFFFFFFu, nn, 1);
    nn += __shfl_xor_sync(0xFFFFFFFFu, nn, 2);

    float s = sqrtf(nn);
    // s' = ||fn||*(dot(p,fn) - dot(c,fn) + MIN_DIST) => s'^2 == signed^2*fnsq
    float outv = (c == 3) ? (MIN_DIST - p) * s : nc * s;

    ((float*)g_face)[4 * (size_t)f + c] = outv;
}

// ---------------------------------------------------------------------------
// Kernel 2: main loop over EXTERIOR points only (~half of all points).
// Interior points need no min: inside => contribution 0. Blocks whose point
// range is beyond the batch's exterior count early-exit (still arrive at the
// completion counter). Padded slots (>= count) read stale-but-masked indices:
// they add a valid subset candidate via atomicMin -> harmless, deterministic.
// Unsigned-min over raw float bits: nonneg floats sort as unsigned; negatives
// sort above all nonnegs -> sign bit set iff ALL signed dists < 0.
// ---------------------------------------------------------------------------
__global__ __launch_bounds__(THREADS)
void dist_kernel(const float* __restrict__ points,
                 const int*   __restrict__ ext,
                 float*       __restrict__ out) {
    __shared__ float4 sf[CHUNK]; // 2 KB

    const int b     = blockIdx.z;
    const int tid   = threadIdx.x;
    const int start = blockIdx.x * PTS_PER_BLOCK;
    const int count = g_pcount[b];

    if (start < count) {
        const float* pp = points + (size_t)b * NP * 3;
        int   pidx[NPTS];
        float PX[NPTS], PY[NPTS], PZ[NPTS];
#pragma unroll
        for (int k = 0; k < NPTS; k++) {
            pidx[k] = g_plist[b * NP + start + tid + k * THREADS] & (NP - 1);
            PX[k] = pp[3 * pidx[k] + 0];
            PY[k] = pp[3 * pidx[k] + 1];
            PZ[k] = pp[3 * pidx[k] + 2];
        }

        sf[tid] = g_face[(size_t)(b * NF + blockIdx.y * CHUNK) + tid];
        __syncthreads();

        unsigned int m[NPTS];
#pragma unroll
        for (int k = 0; k < NPTS; k++) m[k] = 0xFFFFFFFFu;

#pragma unroll 4
        for (int j = 0; j < CHUNK; j++) {
            float4 f = sf[j]; // LDS.128 broadcast (uniform address)
#pragma unroll
            for (int k = 0; k < NPTS; k++) {
                float s = fmaf(PX[k], f.x, fmaf(PY[k], f.y, fmaf(PZ[k], f.z, f.w)));
                m[k] = umin2(m[k], __float_as_uint(s));
            }
        }

#pragma unroll
        for (int k = 0; k < NPTS; k++)
            atomicMin(&g_minbits[b * NP + pidx[k]], m[k]);
    }

    // ---- last-block-done finalize ----
    __shared__ bool is_last;
    __syncthreads(); // all atomics of this block issued
    if (tid == 0) {
        __threadfence();
        unsigned int done = atomicAdd(&g_ctr, 1u);
        is_last = (done == TOTAL_BLOCKS - 1);
    }
    __syncthreads();
    if (!is_last) return;

    __shared__ float red[THREADS];
    float sum = 0.0f;
#pragma unroll 4
    for (int i = tid; i < BB * NP; i += THREADS) {
        unsigned int bits = __ldcg(&g_minbits[i]); // atomics live in L2
        // sign bit set => every signed distance negative => inside
        bool inside = (ext[i] == 0) || (bits & 0x80000000u);
        float mm = __uint_as_float(bits);
        sum += inside ? 0.0f : mm * mm;
    }
    red[tid] = sum;
    __syncthreads();
#pragma unroll
    for (int s = THREADS / 2; s > 0; s >>= 1) {
        if (tid < s) red[tid] += red[tid + s];
        __syncthreads();
    }
    if (tid == 0) {
        out[0] = red[0] * (1.0f / (float)(BB * NP));
        g_ctr = 0; // reset for next graph replay (deterministic)
        g_pcount[0] = 0; g_pcount[1] = 0; g_pcount[2] = 0; g_pcount[3] = 0;
    }
}

// ---------------------------------------------------------------------------
extern "C" void kernel_launch(void* const* d_in, const int* in_sizes, int n_in,
                              void* d_out, int out_size) {
    const float* mesh_V  = (const float*)d_in[0];
    const float* points  = (const float*)d_in[1];
    const float* mesh_FN = (const float*)d_in[2];
    const int*   mesh_F  = (const int*)d_in[3];
    const int*   exterior = (const int*)d_in[4];
    float* out = (float*)d_out;

    (void)in_sizes; (void)n_in; (void)out_size;

    prep_kernel<<<(BB * NF * 4 + 255) / 256, 256>>>(mesh_V, mesh_FN, mesh_F, exterior);

    dim3 grid(PBLOCKS, NCHUNK, BB);
    dist_kernel<<<grid, THREADS>>>(points, exterior, out);
}

// round 16
// speedup vs baseline: 1.8890x; 1.8890x over previous
#include <cuda_runtime.h>

// Problem constants (fixed shapes for this problem instance)
#define BB 4
#define NV 8192
#define NF 8192
#define NP 2048
#define MIN_DIST 0.1f

#define CHUNK 128           // faces per shared-memory tile
#define NCHUNK (NF / CHUNK) // 64
#define THREADS 128
#define NPTS 4              // points per thread
#define PTS_PER_BLOCK (THREADS * NPTS)        // 512
#define PBLOCKS (NP / PTS_PER_BLOCK)          // 4
#define TOTAL_BLOCKS (PBLOCKS * NCHUNK * BB)  // 1024

// Scratch (no allocations allowed in kernel_launch)
__device__ float4       g_face[BB * NF];    // (n'x, n'y, n'z, off') per face
__device__ unsigned int g_minbits[BB * NP]; // unsigned-min of s-bits over faces
__device__ int          g_plist[BB * NP];   // compacted exterior point indices
__device__ int          g_pcount[BB];       // exterior count per batch
__device__ unsigned int g_ctr;              // last-block counter

__device__ __forceinline__ unsigned int umin2(unsigned int a, unsigned int b) {
    return a < b ? a : b; // IMNMX.U32
}

// ---------------------------------------------------------------------------
// Kernel 1: plane precompute (4 threads/face) + minbits init + exterior-point
// compaction (warp-aggregated: 1 atomicAdd per warp, not per thread).
// Compaction order is nondeterministic but the min reduction is order-
// independent, so the final output is deterministic.
// ---------------------------------------------------------------------------
__global__ __launch_bounds__(256)
void prep_kernel(const float* __restrict__ mesh_V,
                 const float* __restrict__ mesh_FN,
                 const int*   __restrict__ mesh_F,
                 const int*   __restrict__ ext) {
    int t = blockIdx.x * blockDim.x + threadIdx.x; // 0 .. BB*NF*4-1
    if (t < BB * NP) { // whole warps (8192 % 32 == 0); one batch per warp
        g_minbits[t] = 0xFFFFFFFFu;
        int b = t / NP;
        bool is_ext = (ext[t] != 0);
        unsigned mask = __ballot_sync(0xFFFFFFFFu, is_ext);
        int lane = t & 31;
        int leader = __ffs(mask) - 1;
        int base = 0;
        if (mask != 0 && lane == leader)
            base = atomicAdd(&g_pcount[b], __popc(mask));
        base = __shfl_sync(0xFFFFFFFFu, base, leader < 0 ? 0 : leader);
        if (is_ext) {
            int off = __popc(mask & ((1u << lane) - 1));
            g_plist[b * NP + base + off] = t - b * NP;
        }
    }

    int f = t >> 2;        // face id (0 .. BB*NF-1)
    int c = t & 3;         // coordinate lane (3 = offset slot)
    if (f >= BB * NF) return;

    int b = f / NF;
    const int* Fp = mesh_F + 3 * f;
    int i0 = Fp[0], i1 = Fp[1], i2 = Fp[2];
    const float* Vb = mesh_V + (size_t)b * NV * 3;

    float cc = 0.0f, nc = 0.0f;
    if (c < 3) {
        cc = (Vb[3 * i0 + c] + Vb[3 * i1 + c] + Vb[3 * i2 + c]) * (1.0f / 3.0f);
        nc = mesh_FN[3 * f + c];
    }

    // 4-lane group sums (groups are lane-aligned: lanes 4k..4k+3)
    float p  = cc * nc;
    float nn = nc * nc;
    p  += __shfl_xor_sync(0xFFFFFFFFu, p, 1);
    p  += __shfl_xor_sync(0xFFFFFFFFu, p, 2);
    nn += __shfl_xor_sync(0xFFFFFFFFu, nn, 1);
    nn += __shfl_xor_sync(0xFFFFFFFFu, nn, 2);

    float s = sqrtf(nn);
    // s' = ||fn||*(dot(p,fn) - dot(c,fn) + MIN_DIST) => s'^2 == signed^2*fnsq
    float outv = (c == 3) ? (MIN_DIST - p) * s : nc * s;

    ((float*)g_face)[4 * (size_t)f + c] = outv;
}

// ---------------------------------------------------------------------------
// Kernel 2: main loop over EXTERIOR points only (~half of all points).
// Interior points contribute 0 regardless of the min -> skipped entirely.
// Blocks whose point range is beyond the batch's exterior count early-exit.
// Pad threads in partially-filled blocks compute on a masked index but their
// atomicMin is GUARDED OUT (R15's regression: unguarded pads all hit index 0,
// serializing tens of thousands of L2 atomics on one address).
// Unsigned-min over raw float bits: nonneg floats sort as unsigned; negatives
// sort above all nonnegs -> sign bit set iff ALL signed dists < 0.
// ---------------------------------------------------------------------------
__global__ __launch_bounds__(THREADS)
void dist_kernel(const float* __restrict__ points,
                 const int*   __restrict__ ext,
                 float*       __restrict__ out) {
    __shared__ float4 sf[CHUNK]; // 2 KB

    const int b     = blockIdx.z;
    const int tid   = threadIdx.x;
    const int start = blockIdx.x * PTS_PER_BLOCK;
    const int count = g_pcount[b];

    if (start < count) {
        const float* pp = points + (size_t)b * NP * 3;
        int   pidx[NPTS];
        bool  valid[NPTS];
        float PX[NPTS], PY[NPTS], PZ[NPTS];
#pragma unroll
        for (int k = 0; k < NPTS; k++) {
            int slot = start + tid + k * THREADS;
            valid[k] = slot < count;
            pidx[k] = g_plist[b * NP + slot] & (NP - 1);
            PX[k] = pp[3 * pidx[k] + 0];
            PY[k] = pp[3 * pidx[k] + 1];
            PZ[k] = pp[3 * pidx[k] + 2];
        }

        sf[tid] = g_face[(size_t)(b * NF + blockIdx.y * CHUNK) + tid];
        __syncthreads();

        unsigned int m[NPTS];
#pragma unroll
        for (int k = 0; k < NPTS; k++) m[k] = 0xFFFFFFFFu;

#pragma unroll 4
        for (int j = 0; j < CHUNK; j++) {
            float4 f = sf[j]; // LDS.128 broadcast (uniform address)
#pragma unroll
            for (int k = 0; k < NPTS; k++) {
                float s = fmaf(PX[k], f.x, fmaf(PY[k], f.y, fmaf(PZ[k], f.z, f.w)));
                m[k] = umin2(m[k], __float_as_uint(s));
            }
        }

#pragma unroll
        for (int k = 0; k < NPTS; k++)
            if (valid[k])
                atomicMin(&g_minbits[b * NP + pidx[k]], m[k]);
    }

    // ---- last-block-done finalize ----
    __shared__ bool is_last;
    __syncthreads(); // all atomics of this block issued
    if (tid == 0) {
        __threadfence();
        unsigned int done = atomicAdd(&g_ctr, 1u);
        is_last = (done == TOTAL_BLOCKS - 1);
    }
    __syncthreads();
    if (!is_last) return;

    __shared__ float red[THREADS];
    float sum = 0.0f;
#pragma unroll 4
    for (int i = tid; i < BB * NP; i += THREADS) {
        unsigned int bits = __ldcg(&g_minbits[i]); // atomics live in L2
        // sign bit set => every signed distance negative => inside
        bool inside = (ext[i] == 0) || (bits & 0x80000000u);
        float mm = __uint_as_float(bits);
        sum += inside ? 0.0f : mm * mm;
    }
    red[tid] = sum;
    __syncthreads();
#pragma unroll
    for (int s = THREADS / 2; s > 0; s >>= 1) {
        if (tid < s) red[tid] += red[tid + s];
        __syncthreads();
    }
    if (tid == 0) {
        out[0] = red[0] * (1.0f / (float)(BB * NP));
        g_ctr = 0; // reset for next graph replay (deterministic)
        g_pcount[0] = 0; g_pcount[1] = 0; g_pcount[2] = 0; g_pcount[3] = 0;
    }
}

// ---------------------------------------------------------------------------
extern "C" void kernel_launch(void* const* d_in, const int* in_sizes, int n_in,
                              void* d_out, int out_size) {
    const float* mesh_V  = (const float*)d_in[0];
    const float* points  = (const float*)d_in[1];
    const float* mesh_FN = (const float*)d_in[2];
    const int*   mesh_F  = (const int*)d_in[3];
    const int*   exterior = (const int*)d_in[4];
    float* out = (float*)d_out;

    (void)in_sizes; (void)n_in; (void)out_size;

    prep_kernel<<<(BB * NF * 4 + 255) / 256, 256>>>(mesh_V, mesh_FN, mesh_F, exterior);

    dim3 grid(PBLOCKS, NCHUNK, BB);
    dist_kernel<<<grid, THREADS>>>(points, exterior, out);
}

// round 17
// speedup vs baseline: 1.8914x; 1.0013x over previous
#include <cuda_runtime.h>

// Problem constants (fixed shapes for this problem instance)
#define BB 4
#define NV 8192
#define NF 8192
#define NP 2048
#define MIN_DIST 0.1f

#define FCHUNK 128          // faces per shared-memory tile
#define NCHUNK (NF / FCHUNK) // 64
#define THREADS 128
#define NPTS 4              // points per thread (contiguous int4 slots)
#define PTS_ITEM (THREADS * NPTS)  // 512 points per work item
#define MAXPB (NP / PTS_ITEM)      // 4
#define GRID_BLOCKS 1024

// Scratch (no allocations allowed in kernel_launch)
__device__ float4       g_face[BB * NF];    // (n'x, n'y, n'z, off') per face
__device__ unsigned int g_minbits[BB * NP]; // unsigned-min of s-bits over faces
__device__ int          g_plist[BB * NP];   // compacted exterior point indices
__device__ int          g_pcount[BB];       // exterior count per batch
__device__ unsigned int g_ticket;           // work-stealing ticket
__device__ unsigned int g_ctr;              // completion counter

__device__ __forceinline__ unsigned int umin2(unsigned int a, unsigned int b) {
    return a < b ? a : b; // IMNMX.U32
}

// ---------------------------------------------------------------------------
// Kernel 1: plane precompute (4 threads/face) + minbits init + exterior-point
// compaction (warp-aggregated atomics). Compaction order nondeterministic but
// min-reduction is order-independent -> deterministic output.
// ---------------------------------------------------------------------------
__global__ __launch_bounds__(256)
void prep_kernel(const float* __restrict__ mesh_V,
                 const float* __restrict__ mesh_FN,
                 const int*   __restrict__ mesh_F,
                 const int*   __restrict__ ext) {
    int t = blockIdx.x * blockDim.x + threadIdx.x; // 0 .. BB*NF*4-1
    if (t < BB * NP) { // whole warps (2048 % 32 == 0); one batch per warp
        g_minbits[t] = 0xFFFFFFFFu;
        int b = t / NP;
        bool is_ext = (ext[t] != 0);
        unsigned mask = __ballot_sync(0xFFFFFFFFu, is_ext);
        int lane = t & 31;
        int leader = __ffs(mask) - 1;
        int base = 0;
        if (mask != 0 && lane == leader)
            base = atomicAdd(&g_pcount[b], __popc(mask));
        base = __shfl_sync(0xFFFFFFFFu, base, leader < 0 ? 0 : leader);
        if (is_ext) {
            int off = __popc(mask & ((1u << lane) - 1));
            g_plist[b * NP + base + off] = t - b * NP;
        }
    }

    int f = t >> 2;        // face id
    int c = t & 3;         // coordinate lane (3 = offset slot)
    if (f >= BB * NF) return;

    int b = f / NF;
    const int* Fp = mesh_F + 3 * f;
    int i0 = Fp[0], i1 = Fp[1], i2 = Fp[2];
    const float* Vb = mesh_V + (size_t)b * NV * 3;

    float cc = 0.0f, nc = 0.0f;
    if (c < 3) {
        cc = (Vb[3 * i0 + c] + Vb[3 * i1 + c] + Vb[3 * i2 + c]) * (1.0f / 3.0f);
        nc = mesh_FN[3 * f + c];
    }

    float p  = cc * nc;
    float nn = nc * nc;
    p  += __shfl_xor_sync(0xFFFFFFFFu, p, 1);
    p  += __shfl_xor_sync(0xFFFFFFFFu, p, 2);
    nn += __shfl_xor_sync(0xFFFFFFFFu, nn, 1);
    nn += __shfl_xor_sync(0xFFFFFFFFu, nn, 2);

    float s = sqrtf(nn);
    // s' = ||fn||*(dot(p,fn) - dot(c,fn) + MIN_DIST) => s'^2 == signed^2*fnsq
    float outv = (c == 3) ? (MIN_DIST - p) * s : nc * s;

    ((float*)g_face)[4 * (size_t)f + c] = outv;
}

// ---------------------------------------------------------------------------
// Kernel 2: work-stealing main loop over EXTERIOR points only.
// Item = (batch, point-block of 512 compacted slots, 128-face chunk), taken
// from a global ticket -> SM load balance independent of placement LUT
// congruences (R16's 2x imbalance: active bids = 0,1 mod 4 and 148 = 0 mod 4
// starved half the SMs). Warps whose 128-slot range is fully past the count
// skip the face loop. Per-thread pad slots compute on masked data; only the
// atomicMin is guarded. Last finishing block reduces + resets counters.
// ---------------------------------------------------------------------------
__global__ __launch_bounds__(THREADS)
void dist_kernel(const float* __restrict__ points,
                 const int*   __restrict__ ext,
                 float*       __restrict__ out) {
    __shared__ float4 sf[FCHUNK]; // 2 KB
    __shared__ int s_ticket;

    const int tid = threadIdx.x;
    const int wid = tid >> 5;

    // per-block decode tables (uniform, from L2)
    int cnt[BB], npb[BB], items[BB];
    int T = 0;
#pragma unroll
    for (int b = 0; b < BB; b++) {
        cnt[b] = g_pcount[b];
        int n = (cnt[b] + PTS_ITEM - 1) / PTS_ITEM;
        npb[b] = n > MAXPB ? MAXPB : n;
        items[b] = npb[b] * NCHUNK;
        T += items[b];
    }

    while (true) {
        if (tid == 0) s_ticket = atomicAdd(&g_ticket, 1u);
        __syncthreads(); // publish ticket; also: prior item's sf reads done
        int it = s_ticket;
        if (it >= T) break;

        int b = 0;
#pragma unroll
        for (int k = 0; k < BB - 1; k++)
            if (it >= items[b]) { it -= items[b]; b++; }
        int pb    = it % npb[b];
        int chunk = it / npb[b];
        int count = cnt[b];

        sf[tid] = g_face[(size_t)(b * NF + chunk * FCHUNK) + tid];
        __syncthreads();

        // warp-level skip: this warp's 128 slots all >= count?
        int wbase = pb * PTS_ITEM + wid * (32 * NPTS);
        if (wbase < count) {
            const float* pp = points + (size_t)b * NP * 3;
            int4 sl = *(const int4*)&g_plist[b * NP + pb * PTS_ITEM + tid * NPTS];
            int pidx[NPTS] = { sl.x & (NP - 1), sl.y & (NP - 1),
                               sl.z & (NP - 1), sl.w & (NP - 1) };
            float PX[NPTS], PY[NPTS], PZ[NPTS];
#pragma unroll
            for (int k = 0; k < NPTS; k++) {
                PX[k] = pp[3 * pidx[k] + 0];
                PY[k] = pp[3 * pidx[k] + 1];
                PZ[k] = pp[3 * pidx[k] + 2];
            }

            unsigned int m[NPTS];
#pragma unroll
            for (int k = 0; k < NPTS; k++) m[k] = 0xFFFFFFFFu;

#pragma unroll 4
            for (int j = 0; j < FCHUNK; j++) {
                float4 f = sf[j]; // LDS.128 broadcast (uniform address)
#pragma unroll
                for (int k = 0; k < NPTS; k++) {
                    float s = fmaf(PX[k], f.x, fmaf(PY[k], f.y, fmaf(PZ[k], f.z, f.w)));
                    m[k] = umin2(m[k], __float_as_uint(s));
                }
            }

            int sbase = pb * PTS_ITEM + tid * NPTS;
#pragma unroll
            for (int k = 0; k < NPTS; k++)
                if (sbase + k < count)
                    atomicMin(&g_minbits[b * NP + pidx[k]], m[k]);
        }
    }

    // ---- last-block-done finalize ----
    __shared__ bool is_last;
    if (tid == 0) {
        __threadfence();
        unsigned int done = atomicAdd(&g_ctr, 1u);
        is_last = (done == GRID_BLOCKS - 1);
    }
    __syncthreads();
    if (!is_last) return;

    __shared__ float red[THREADS];
    float sum = 0.0f;
#pragma unroll 4
    for (int i = tid; i < BB * NP; i += THREADS) {
        unsigned int bits = __ldcg(&g_minbits[i]); // atomics live in L2
        // sign bit set => every signed distance negative => inside
        bool inside = (ext[i] == 0) || (bits & 0x80000000u);
        float mm = __uint_as_float(bits);
        sum += inside ? 0.0f : mm * mm;
    }
    red[tid] = sum;
    __syncthreads();
#pragma unroll
    for (int s = THREADS / 2; s > 0; s >>= 1) {
        if (tid < s) red[tid] += red[tid + s];
        __syncthreads();
    }
    if (tid == 0) {
        out[0] = red[0] * (1.0f / (float)(BB * NP));
        g_ctr = 0;      // reset for next graph replay (deterministic)
        g_ticket = 0;
        g_pcount[0] = 0; g_pcount[1] = 0; g_pcount[2] = 0; g_pcount[3] = 0;
    }
}

// ---------------------------------------------------------------------------
extern "C" void kernel_launch(void* const* d_in, const int* in_sizes, int n_in,
                              void* d_out, int out_size) {
    const float* mesh_V  = (const float*)d_in[0];
    const float* points  = (const float*)d_in[1];
    const float* mesh_FN = (const float*)d_in[2];
    const int*   mesh_F  = (const int*)d_in[3];
    const int*   exterior = (const int*)d_in[4];
    float* out = (float*)d_out;

    (void)in_sizes; (void)n_in; (void)out_size;

    prep_kernel<<<(BB * NF * 4 + 255) / 256, 256>>>(mesh_V, mesh_FN, mesh_F, exterior);

    dist_kernel<<<GRID_BLOCKS, THREADS>>>(points, exterior, out);
}